// round 1
// baseline (speedup 1.0000x reference)
#include <cuda_runtime.h>
#include <cuda_bf16.h>

// Problem shape (fixed by reference setup_inputs)
#define B 64
#define T 4096
#define H 512

// Scratch (no allocation allowed in kernel_launch)
__device__ float g_v[B * H];        // v = hidden @ W   [B, H]
__device__ float g_scores[B * T];   // raw scores       [B, T]

// ---------------------------------------------------------------------------
// Kernel 1: v[b,h] = sum_o hidden[b,o] * W[o,h]
// Grid: B blocks, H threads. hidden row staged in smem; W column walk is
// coalesced (consecutive h per warp). W (1MB) stays L2-resident across blocks.
// ---------------------------------------------------------------------------
__global__ void proj_hidden_kernel(const float* __restrict__ hidden,
                                   const float* __restrict__ W) {
    const int b = blockIdx.x;
    const int h = threadIdx.x;
    __shared__ float sh[H];
    sh[h] = hidden[b * H + h];
    __syncthreads();

    float acc = 0.0f;
#pragma unroll 8
    for (int o = 0; o < H; ++o) {
        acc += sh[o] * W[o * H + h];
    }
    g_v[b * H + h] = acc;
}

// ---------------------------------------------------------------------------
// Kernel 2: scores[b,t] = enc[b,t,:] . v[b,:]
// Grid: (T/64, B). 256 threads = 8 warps; each warp owns 8 consecutive t.
// Per t: 4 x float4 coalesced loads per lane (512B/warp per step), dot with
// v staged in smem, butterfly warp reduction.
// ---------------------------------------------------------------------------
__global__ void scores_kernel(const float* __restrict__ enc) {
    const int b    = blockIdx.y;
    const int tile = blockIdx.x;          // 64 t-values per block
    const int tid  = threadIdx.x;         // 256
    const int warp = tid >> 5;
    const int lane = tid & 31;

    __shared__ float sv[H];
    // 256 threads x float2 = 512 floats
    reinterpret_cast<float2*>(sv)[tid] =
        reinterpret_cast<const float2*>(g_v + b * H)[tid];
    __syncthreads();

    const float4* __restrict__ vb = reinterpret_cast<const float4*>(sv);
    const float4* __restrict__ base =
        reinterpret_cast<const float4*>(enc + (size_t)b * T * H);

#pragma unroll
    for (int i = 0; i < 8; ++i) {
        const int t = tile * 64 + warp * 8 + i;
        const float4* __restrict__ row = base + (size_t)t * (H / 4);

        float acc = 0.0f;
#pragma unroll
        for (int k = 0; k < 4; ++k) {
            const float4 x = row[lane + k * 32];
            const float4 w = vb[lane + k * 32];
            acc += x.x * w.x + x.y * w.y + x.z * w.z + x.w * w.w;
        }
#pragma unroll
        for (int off = 16; off; off >>= 1)
            acc += __shfl_xor_sync(0xffffffffu, acc, off);
        if (lane == 0) g_scores[b * T + t] = acc;
    }
}

// ---------------------------------------------------------------------------
// Kernel 3: row softmax over T. One block per b, 1024 threads, float4/thread.
// ---------------------------------------------------------------------------
__global__ void softmax_kernel(float* __restrict__ out) {
    const int b   = blockIdx.x;
    const int tid = threadIdx.x;          // 1024
    const int warp = tid >> 5;
    const int lane = tid & 31;

    const float4 x = reinterpret_cast<const float4*>(g_scores + b * T)[tid];

    __shared__ float red[32];
    __shared__ float sbc;

    // --- block max ---
    float m = fmaxf(fmaxf(x.x, x.y), fmaxf(x.z, x.w));
#pragma unroll
    for (int off = 16; off; off >>= 1)
        m = fmaxf(m, __shfl_xor_sync(0xffffffffu, m, off));
    if (lane == 0) red[warp] = m;
    __syncthreads();
    if (tid < 32) {
        float mm = red[tid];
#pragma unroll
        for (int off = 16; off; off >>= 1)
            mm = fmaxf(mm, __shfl_xor_sync(0xffffffffu, mm, off));
        if (tid == 0) sbc = mm;
    }
    __syncthreads();
    m = sbc;

    // --- exp + block sum ---
    const float e0 = expf(x.x - m);
    const float e1 = expf(x.y - m);
    const float e2 = expf(x.z - m);
    const float e3 = expf(x.w - m);
    float s = (e0 + e1) + (e2 + e3);
#pragma unroll
    for (int off = 16; off; off >>= 1)
        s += __shfl_xor_sync(0xffffffffu, s, off);
    __syncthreads();   // protect red[] reuse
    if (lane == 0) red[warp] = s;
    __syncthreads();
    if (tid < 32) {
        float ss = red[tid];
#pragma unroll
        for (int off = 16; off; off >>= 1)
            ss += __shfl_xor_sync(0xffffffffu, ss, off);
        if (tid == 0) sbc = ss;
    }
    __syncthreads();
    const float inv = 1.0f / sbc;

    float4 y;
    y.x = e0 * inv; y.y = e1 * inv; y.z = e2 * inv; y.w = e3 * inv;
    reinterpret_cast<float4*>(out + b * T)[tid] = y;
}

// ---------------------------------------------------------------------------
extern "C" void kernel_launch(void* const* d_in, const int* in_sizes, int n_in,
                              void* d_out, int out_size) {
    const float* hidden = (const float*)d_in[0];   // [B, H]
    const float* enc    = (const float*)d_in[1];   // [B, T, H]
    const float* W      = (const float*)d_in[2];   // [H, H]
    // d_in[3] = bias: cancels under softmax, unused.
    float* out = (float*)d_out;                    // [B, 1, T]

    proj_hidden_kernel<<<B, H>>>(hidden, W);
    {
        dim3 grid(T / 64, B);
        scores_kernel<<<grid, 256>>>(enc);
    }
    softmax_kernel<<<B, 1024>>>(out);
}

// round 2
// speedup vs baseline: 1.2660x; 1.2660x over previous
#include <cuda_runtime.h>
#include <cuda_bf16.h>

// Problem shape (fixed by reference setup_inputs)
#define B 64
#define T 4096
#define H 512

// Scratch (no allocation allowed in kernel_launch)
__device__ float g_v[B * H];        // v = hidden @ W   [B, H]
__device__ float g_scores[B * T];   // raw scores       [B, T]

// ---------------------------------------------------------------------------
// Kernel 1: v[b,h] = sum_o hidden[b,o] * W[o,h]
// Grid: (H/32, B/8) = 128 blocks, 256 threads, ONE output per thread.
// 8 hidden rows staged in smem (broadcast reads). W reads: each warp pulls a
// coalesced 128B slice W[o, h0:h0+32] per K step; same slice reused by all 8
// warps (L1 hit) and by the 8 b-group blocks (L2 hit). W DRAM traffic = 1MB.
// ---------------------------------------------------------------------------
__global__ void proj_hidden_kernel(const float* __restrict__ hidden,
                                   const float* __restrict__ W) {
    const int lane   = threadIdx.x & 31;
    const int blocal = threadIdx.x >> 5;                 // 0..7 (warp = b row)
    const int h      = blockIdx.x * 32 + lane;
    const int bbase  = blockIdx.y * 8;

    __shared__ float sh[8][H];
    // stage 8 hidden rows: 8*512 floats, 256 threads -> 4 float4 each
    for (int i = threadIdx.x; i < 8 * (H / 4); i += 256) {
        const int r = i >> 7;            // / (H/4)
        const int c = i & 127;           // % (H/4)
        reinterpret_cast<float4*>(sh[r])[c] =
            reinterpret_cast<const float4*>(hidden + (size_t)(bbase + r) * H)[c];
    }
    __syncthreads();

    const float* __restrict__ wcol = W + h;
    float acc = 0.0f;
#pragma unroll 16
    for (int o = 0; o < H; ++o) {
        acc += sh[blocal][o] * wcol[(size_t)o * H];
    }
    g_v[(size_t)(bbase + blocal) * H + h] = acc;
}

// ---------------------------------------------------------------------------
// Kernel 2: scores[b,t] = enc[b,t,:] . v[b,:]
// Grid: (T/64, B). 256 threads = 8 warps; each warp owns 8 consecutive t.
// __ldcs on enc: single-use 512MB stream, evict-first so L2 keeps W/v/scores.
// ---------------------------------------------------------------------------
__global__ void scores_kernel(const float* __restrict__ enc) {
    const int b    = blockIdx.y;
    const int tile = blockIdx.x;          // 64 t-values per block
    const int tid  = threadIdx.x;         // 256
    const int warp = tid >> 5;
    const int lane = tid & 31;

    __shared__ float sv[H];
    reinterpret_cast<float2*>(sv)[tid] =
        reinterpret_cast<const float2*>(g_v + b * H)[tid];
    __syncthreads();

    const float4* __restrict__ vb = reinterpret_cast<const float4*>(sv);
    const float4* __restrict__ base =
        reinterpret_cast<const float4*>(enc + (size_t)b * T * H);

#pragma unroll
    for (int i = 0; i < 8; ++i) {
        const int t = tile * 64 + warp * 8 + i;
        const float4* __restrict__ row = base + (size_t)t * (H / 4);

        float acc = 0.0f;
#pragma unroll
        for (int k = 0; k < 4; ++k) {
            const float4 x = __ldcs(row + lane + k * 32);
            const float4 w = vb[lane + k * 32];
            acc += x.x * w.x + x.y * w.y + x.z * w.z + x.w * w.w;
        }
#pragma unroll
        for (int off = 16; off; off >>= 1)
            acc += __shfl_xor_sync(0xffffffffu, acc, off);
        if (lane == 0) g_scores[b * T + t] = acc;
    }
}

// ---------------------------------------------------------------------------
// Kernel 3: row softmax over T. One block per b, 1024 threads, float4/thread.
// ---------------------------------------------------------------------------
__global__ void softmax_kernel(float* __restrict__ out) {
    const int b   = blockIdx.x;
    const int tid = threadIdx.x;          // 1024
    const int warp = tid >> 5;
    const int lane = tid & 31;

    const float4 x = reinterpret_cast<const float4*>(g_scores + b * T)[tid];

    __shared__ float red[32];
    __shared__ float sbc;

    // --- block max ---
    float m = fmaxf(fmaxf(x.x, x.y), fmaxf(x.z, x.w));
#pragma unroll
    for (int off = 16; off; off >>= 1)
        m = fmaxf(m, __shfl_xor_sync(0xffffffffu, m, off));
    if (lane == 0) red[warp] = m;
    __syncthreads();
    if (tid < 32) {
        float mm = red[tid];
#pragma unroll
        for (int off = 16; off; off >>= 1)
            mm = fmaxf(mm, __shfl_xor_sync(0xffffffffu, mm, off));
        if (tid == 0) sbc = mm;
    }
    __syncthreads();
    m = sbc;

    // --- exp + block sum ---
    const float e0 = expf(x.x - m);
    const float e1 = expf(x.y - m);
    const float e2 = expf(x.z - m);
    const float e3 = expf(x.w - m);
    float s = (e0 + e1) + (e2 + e3);
#pragma unroll
    for (int off = 16; off; off >>= 1)
        s += __shfl_xor_sync(0xffffffffu, s, off);
    __syncthreads();   // protect red[] reuse
    if (lane == 0) red[warp] = s;
    __syncthreads();
    if (tid < 32) {
        float ss = red[tid];
#pragma unroll
        for (int off = 16; off; off >>= 1)
            ss += __shfl_xor_sync(0xffffffffu, ss, off);
        if (tid == 0) sbc = ss;
    }
    __syncthreads();
    const float inv = 1.0f / sbc;

    float4 y;
    y.x = e0 * inv; y.y = e1 * inv; y.z = e2 * inv; y.w = e3 * inv;
    reinterpret_cast<float4*>(out + b * T)[tid] = y;
}

// ---------------------------------------------------------------------------
extern "C" void kernel_launch(void* const* d_in, const int* in_sizes, int n_in,
                              void* d_out, int out_size) {
    const float* hidden = (const float*)d_in[0];   // [B, H]
    const float* enc    = (const float*)d_in[1];   // [B, T, H]
    const float* W      = (const float*)d_in[2];   // [H, H]
    // d_in[3] = bias: cancels under softmax, unused.
    float* out = (float*)d_out;                    // [B, 1, T]

    {
        dim3 grid(H / 32, B / 8);
        proj_hidden_kernel<<<grid, 256>>>(hidden, W);
    }
    {
        dim3 grid(T / 64, B);
        scores_kernel<<<grid, 256>>>(enc);
    }
    softmax_kernel<<<B, 1024>>>(out);
}

// round 3
// speedup vs baseline: 1.3538x; 1.0694x over previous
#include <cuda_runtime.h>
#include <cuda_bf16.h>

// Problem shape (fixed by reference setup_inputs)
#define B 64
#define T 4096
#define H 512

// Scratch (no allocation allowed in kernel_launch)
__device__ float g_v[B * H];        // v = hidden @ W   [B, H]
__device__ float g_scores[B * T];   // raw scores       [B, T]

// ---------------------------------------------------------------------------
// Kernel 1: v[b,h] = sum_o hidden[b,o] * W[o,h]
// Grid: (H/64, B) = 512 blocks, 256 threads = (64 h-lanes x 4 o-groups).
// Each o-group covers 128 of the 512 K-steps -> 4x MLP & 4x block count vs R2.
// All blocks co-resident (~28 warps/SM) so the 234cyc L2 latency on the W
// column walk is hidden. Cross-group reduction through 1KB smem.
// ---------------------------------------------------------------------------
__global__ void proj_hidden_kernel(const float* __restrict__ hidden,
                                   const float* __restrict__ W) {
    const int b  = blockIdx.y;
    const int h0 = blockIdx.x * 64;
    const int hl = threadIdx.x & 63;     // h lane within tile
    const int og = threadIdx.x >> 6;     // o-group 0..3

    __shared__ float sh[H];
    // stage hidden row: 512 floats / 256 threads -> float2 each
    reinterpret_cast<float2*>(sh)[threadIdx.x] =
        reinterpret_cast<const float2*>(hidden + (size_t)b * H)[threadIdx.x];
    __syncthreads();

    const float* __restrict__ wp = W + (size_t)(og * 128) * H + h0 + hl;
    const float* __restrict__ hp = sh + og * 128;
    float acc = 0.0f;
#pragma unroll 16
    for (int o = 0; o < 128; ++o) {
        acc += hp[o] * wp[(size_t)o * H];
    }

    __shared__ float part[4][64];
    part[og][hl] = acc;
    __syncthreads();
    if (threadIdx.x < 64) {
        const float r = (part[0][threadIdx.x] + part[1][threadIdx.x])
                      + (part[2][threadIdx.x] + part[3][threadIdx.x]);
        g_v[(size_t)b * H + h0 + threadIdx.x] = r;
    }
}

// ---------------------------------------------------------------------------
// Kernel 2: scores[b,t] = enc[b,t,:] . v[b,:]
// Grid: (T/64, B). 256 threads = 8 warps; each warp owns 8 consecutive t.
// __ldcs on enc: single-use 512MB stream, evict-first so L2 keeps W/v/scores.
// ---------------------------------------------------------------------------
__global__ void scores_kernel(const float* __restrict__ enc) {
    const int b    = blockIdx.y;
    const int tile = blockIdx.x;          // 64 t-values per block
    const int tid  = threadIdx.x;         // 256
    const int warp = tid >> 5;
    const int lane = tid & 31;

    __shared__ float sv[H];
    reinterpret_cast<float2*>(sv)[tid] =
        reinterpret_cast<const float2*>(g_v + b * H)[tid];
    __syncthreads();

    const float4* __restrict__ vb = reinterpret_cast<const float4*>(sv);
    const float4* __restrict__ base =
        reinterpret_cast<const float4*>(enc + (size_t)b * T * H);

#pragma unroll
    for (int i = 0; i < 8; ++i) {
        const int t = tile * 64 + warp * 8 + i;
        const float4* __restrict__ row = base + (size_t)t * (H / 4);

        float acc = 0.0f;
#pragma unroll
        for (int k = 0; k < 4; ++k) {
            const float4 x = __ldcs(row + lane + k * 32);
            const float4 w = vb[lane + k * 32];
            acc += x.x * w.x + x.y * w.y + x.z * w.z + x.w * w.w;
        }
#pragma unroll
        for (int off = 16; off; off >>= 1)
            acc += __shfl_xor_sync(0xffffffffu, acc, off);
        if (lane == 0) g_scores[b * T + t] = acc;
    }
}

// ---------------------------------------------------------------------------
// Kernel 3: row softmax over T. One block per b, 1024 threads, float4/thread.
// ---------------------------------------------------------------------------
__global__ void softmax_kernel(float* __restrict__ out) {
    const int b   = blockIdx.x;
    const int tid = threadIdx.x;          // 1024
    const int warp = tid >> 5;
    const int lane = tid & 31;

    const float4 x = reinterpret_cast<const float4*>(g_scores + b * T)[tid];

    __shared__ float red[32];
    __shared__ float sbc;

    // --- block max ---
    float m = fmaxf(fmaxf(x.x, x.y), fmaxf(x.z, x.w));
#pragma unroll
    for (int off = 16; off; off >>= 1)
        m = fmaxf(m, __shfl_xor_sync(0xffffffffu, m, off));
    if (lane == 0) red[warp] = m;
    __syncthreads();
    if (tid < 32) {
        float mm = red[tid];
#pragma unroll
        for (int off = 16; off; off >>= 1)
            mm = fmaxf(mm, __shfl_xor_sync(0xffffffffu, mm, off));
        if (tid == 0) sbc = mm;
    }
    __syncthreads();
    m = sbc;

    // --- exp + block sum ---
    const float e0 = expf(x.x - m);
    const float e1 = expf(x.y - m);
    const float e2 = expf(x.z - m);
    const float e3 = expf(x.w - m);
    float s = (e0 + e1) + (e2 + e3);
#pragma unroll
    for (int off = 16; off; off >>= 1)
        s += __shfl_xor_sync(0xffffffffu, s, off);
    __syncthreads();   // protect red[] reuse
    if (lane == 0) red[warp] = s;
    __syncthreads();
    if (tid < 32) {
        float ss = red[tid];
#pragma unroll
        for (int off = 16; off; off >>= 1)
            ss += __shfl_xor_sync(0xffffffffu, ss, off);
        if (tid == 0) sbc = ss;
    }
    __syncthreads();
    const float inv = 1.0f / sbc;

    float4 y;
    y.x = e0 * inv; y.y = e1 * inv; y.z = e2 * inv; y.w = e3 * inv;
    reinterpret_cast<float4*>(out + b * T)[tid] = y;
}

// ---------------------------------------------------------------------------
extern "C" void kernel_launch(void* const* d_in, const int* in_sizes, int n_in,
                              void* d_out, int out_size) {
    const float* hidden = (const float*)d_in[0];   // [B, H]
    const float* enc    = (const float*)d_in[1];   // [B, T, H]
    const float* W      = (const float*)d_in[2];   // [H, H]
    // d_in[3] = bias: cancels under softmax, unused.
    float* out = (float*)d_out;                    // [B, 1, T]

    {
        dim3 grid(H / 64, B);
        proj_hidden_kernel<<<grid, 256>>>(hidden, W);
    }
    {
        dim3 grid(T / 64, B);
        scores_kernel<<<grid, 256>>>(enc);
    }
    softmax_kernel<<<B, 1024>>>(out);
}

// round 4
// speedup vs baseline: 1.3845x; 1.0227x over previous
#include <cuda_runtime.h>
#include <cuda_bf16.h>

// Problem shape (fixed by reference setup_inputs)
#define B 64
#define T 4096
#define H 512

// Scratch (no allocation allowed in kernel_launch)
__device__ float g_v[B * H];        // v = hidden @ W   [B, H]
__device__ float g_scores[B * T];   // raw scores       [B, T]

// ---------------------------------------------------------------------------
// Kernel 1: v[b,h] = sum_o hidden[b,o] * W[o,h]
// Grid: (H/32, B/2) = 512 blocks, 256 threads = 32 h-lanes x 8 o-groups.
// Each thread: 64 o-steps, one coalesced W load per step, reused for 2 b's
// (acc[2]) -> W L2 traffic halved to 32MB. og is warp-uniform so every W
// load is one 128B wavefront. Cross-og reduction via smem.
// ---------------------------------------------------------------------------
__global__ void proj_hidden_kernel(const float* __restrict__ hidden,
                                   const float* __restrict__ W) {
    const int b0 = blockIdx.y * 2;
    const int h0 = blockIdx.x * 32;
    const int hl = threadIdx.x & 31;     // h lane
    const int og = threadIdx.x >> 5;     // o-group 0..7 (warp-uniform)

    __shared__ float sh[2][H];
    // stage 2 hidden rows: 1024 floats / 256 threads -> float4 each
    {
        const int r = threadIdx.x >> 7;          // 0..1
        const int c = threadIdx.x & 127;         // 0..127 float4 slots
        reinterpret_cast<float4*>(sh[r])[c] =
            reinterpret_cast<const float4*>(hidden + (size_t)(b0 + r) * H)[c];
    }
    __syncthreads();

    const float* __restrict__ wp = W + (size_t)(og * 64) * H + h0 + hl;
    const float* __restrict__ h0p = sh[0] + og * 64;
    const float* __restrict__ h1p = sh[1] + og * 64;
    float acc0 = 0.0f, acc1 = 0.0f;
#pragma unroll 16
    for (int o = 0; o < 64; ++o) {
        const float w = wp[(size_t)o * H];
        acc0 += h0p[o] * w;
        acc1 += h1p[o] * w;
    }

    __shared__ float part[8][2][32];
    part[og][0][hl] = acc0;
    part[og][1][hl] = acc1;
    __syncthreads();
    if (threadIdx.x < 64) {
        const int bb = threadIdx.x >> 5;
        const int hh = threadIdx.x & 31;
        float r = 0.0f;
#pragma unroll
        for (int g = 0; g < 8; ++g) r += part[g][bb][hh];
        g_v[(size_t)(b0 + bb) * H + h0 + hh] = r;
    }
}

// ---------------------------------------------------------------------------
// Kernel 2: scores[b,t] = enc[b,t,:] . v[b,:]
// Grid: (T/64, B). 256 threads = 8 warps; each warp owns 8 consecutive t.
// __ldcs on enc: single-use 512MB stream, evict-first so L2 keeps W/v/scores.
// ---------------------------------------------------------------------------
__global__ void scores_kernel(const float* __restrict__ enc) {
    const int b    = blockIdx.y;
    const int tile = blockIdx.x;          // 64 t-values per block
    const int tid  = threadIdx.x;         // 256
    const int warp = tid >> 5;
    const int lane = tid & 31;

    __shared__ float sv[H];
    reinterpret_cast<float2*>(sv)[tid] =
        reinterpret_cast<const float2*>(g_v + b * H)[tid];
    __syncthreads();

    const float4* __restrict__ vb = reinterpret_cast<const float4*>(sv);
    const float4* __restrict__ base =
        reinterpret_cast<const float4*>(enc + (size_t)b * T * H);

#pragma unroll
    for (int i = 0; i < 8; ++i) {
        const int t = tile * 64 + warp * 8 + i;
        const float4* __restrict__ row = base + (size_t)t * (H / 4);

        float acc = 0.0f;
#pragma unroll
        for (int k = 0; k < 4; ++k) {
            const float4 x = __ldcs(row + lane + k * 32);
            const float4 w = vb[lane + k * 32];
            acc += x.x * w.x + x.y * w.y + x.z * w.z + x.w * w.w;
        }
#pragma unroll
        for (int off = 16; off; off >>= 1)
            acc += __shfl_xor_sync(0xffffffffu, acc, off);
        if (lane == 0) g_scores[b * T + t] = acc;
    }
}

// ---------------------------------------------------------------------------
// Kernel 3: row softmax over T. One block per b, 1024 threads, float4/thread.
// ---------------------------------------------------------------------------
__global__ void softmax_kernel(float* __restrict__ out) {
    const int b   = blockIdx.x;
    const int tid = threadIdx.x;          // 1024
    const int warp = tid >> 5;
    const int lane = tid & 31;

    const float4 x = reinterpret_cast<const float4*>(g_scores + b * T)[tid];

    __shared__ float red[32];
    __shared__ float sbc;

    // --- block max ---
    float m = fmaxf(fmaxf(x.x, x.y), fmaxf(x.z, x.w));
#pragma unroll
    for (int off = 16; off; off >>= 1)
        m = fmaxf(m, __shfl_xor_sync(0xffffffffu, m, off));
    if (lane == 0) red[warp] = m;
    __syncthreads();
    if (tid < 32) {
        float mm = red[tid];
#pragma unroll
        for (int off = 16; off; off >>= 1)
            mm = fmaxf(mm, __shfl_xor_sync(0xffffffffu, mm, off));
        if (tid == 0) sbc = mm;
    }
    __syncthreads();
    m = sbc;

    // --- exp + block sum ---
    const float e0 = expf(x.x - m);
    const float e1 = expf(x.y - m);
    const float e2 = expf(x.z - m);
    const float e3 = expf(x.w - m);
    float s = (e0 + e1) + (e2 + e3);
#pragma unroll
    for (int off = 16; off; off >>= 1)
        s += __shfl_xor_sync(0xffffffffu, s, off);
    __syncthreads();   // protect red[] reuse
    if (lane == 0) red[warp] = s;
    __syncthreads();
    if (tid < 32) {
        float ss = red[tid];
#pragma unroll
        for (int off = 16; off; off >>= 1)
            ss += __shfl_xor_sync(0xffffffffu, ss, off);
        if (tid == 0) sbc = ss;
    }
    __syncthreads();
    const float inv = 1.0f / sbc;

    float4 y;
    y.x = e0 * inv; y.y = e1 * inv; y.z = e2 * inv; y.w = e3 * inv;
    reinterpret_cast<float4*>(out + b * T)[tid] = y;
}

// ---------------------------------------------------------------------------
extern "C" void kernel_launch(void* const* d_in, const int* in_sizes, int n_in,
                              void* d_out, int out_size) {
    const float* hidden = (const float*)d_in[0];   // [B, H]
    const float* enc    = (const float*)d_in[1];   // [B, T, H]
    const float* W      = (const float*)d_in[2];   // [H, H]
    // d_in[3] = bias: cancels under softmax, unused.
    float* out = (float*)d_out;                    // [B, 1, T]

    {
        dim3 grid(H / 32, B / 2);
        proj_hidden_kernel<<<grid, 256>>>(hidden, W);
    }
    {
        dim3 grid(T / 64, B);
        scores_kernel<<<grid, 256>>>(enc);
    }
    softmax_kernel<<<B, 1024>>>(out);
}